// round 15
// baseline (speedup 1.0000x reference)
#include <cuda_runtime.h>
#include <cuda_bf16.h>
#include <cstddef>
#include <cstdint>
#include <math.h>

#define SEQ   512
#define BATCH 256
#define INP   256
#define HID   512

typedef unsigned long long u64;

// ---------- sync helpers ----------
__device__ __forceinline__ unsigned ld_acq(const unsigned* p) {
    unsigned v;
    asm volatile("ld.acquire.gpu.global.b32 %0,[%1];" : "=r"(v) : "l"(p) : "memory");
    return v;
}
__device__ __forceinline__ void st_rel(unsigned* p, unsigned v) {
    asm volatile("st.release.gpu.global.b32 [%0],%1;" :: "l"(p), "r"(v) : "memory");
}

// ---------- fast activations ----------
__device__ __forceinline__ float sig_f(float z) {
    return __fdividef(1.0f, 1.0f + __expf(-z));
}
__device__ __forceinline__ float tanh_f(float z) {
    return 1.0f - __fdividef(2.0f, __expf(2.0f * z) + 1.0f);
}

// ---------- scratch ----------
__device__ float g_xp[(size_t)SEQ * BATCH * 3 * HID];
__device__ uint32_t g_hb[2][2][BATCH * HID / 2];   // [buf][plane hi/lo][b*256 + j/2]
__device__ unsigned g_flags[8][32];                // [bt][jt] monotonic step flags
__device__ __nv_bfloat16 g_xh[(size_t)SEQ * BATCH * INP];
__device__ __nv_bfloat16 g_xl[(size_t)SEQ * BATCH * INP];
__device__ __nv_bfloat16 g_uh[3 * HID * INP];
__device__ __nv_bfloat16 g_ul[3 * HID * INP];

// ---------- split helpers ----------
__device__ __forceinline__ uint32_t pck(__nv_bfloat16 a, __nv_bfloat16 b) {
    return (uint32_t)__bfloat16_as_ushort(a) | ((uint32_t)__bfloat16_as_ushort(b) << 16);
}
__device__ __forceinline__ void split4(float4 v, uint2& hi, uint2& lo) {
    __nv_bfloat16 h0 = __float2bfloat16_rn(v.x), h1 = __float2bfloat16_rn(v.y);
    __nv_bfloat16 h2 = __float2bfloat16_rn(v.z), h3 = __float2bfloat16_rn(v.w);
    __nv_bfloat16 l0 = __float2bfloat16_rn(v.x - __bfloat162float(h0));
    __nv_bfloat16 l1 = __float2bfloat16_rn(v.y - __bfloat162float(h1));
    __nv_bfloat16 l2 = __float2bfloat16_rn(v.z - __bfloat162float(h2));
    __nv_bfloat16 l3 = __float2bfloat16_rn(v.w - __bfloat162float(h3));
    hi = make_uint2(pck(h0, h1), pck(h2, h3));
    lo = make_uint2(pck(l0, l1), pck(l2, l3));
}

__global__ void __launch_bounds__(256) xsplit_kernel(const float* __restrict__ X) {
    const size_t total = (size_t)SEQ * BATCH * INP / 4;
    for (size_t f4 = (size_t)blockIdx.x * 256 + threadIdx.x; f4 < total;
         f4 += (size_t)gridDim.x * 256) {
        float4 v = __ldcg((const float4*)X + f4);
        uint2 hi, lo; split4(v, hi, lo);
        ((uint2*)g_xh)[f4] = hi;
        ((uint2*)g_xl)[f4] = lo;
    }
}

__global__ void __launch_bounds__(256) usplit_kernel(
    const float* __restrict__ Uc, const float* __restrict__ Ua,
    const float* __restrict__ Uh)
{
    const int mat = blockIdx.x >> 7;
    const int f4 = (blockIdx.x & 127) * 256 + threadIdx.x;
    const float* src = (mat == 0) ? Uc : (mat == 1 ? Ua : Uh);
    float4 v = __ldcg((const float4*)src + f4);
    uint2 hi, lo; split4(v, hi, lo);
    ((uint2*)g_uh)[mat * 32768 + f4] = hi;
    ((uint2*)g_ul)[mat * 32768 + f4] = lo;
}

// ---------- mma / ldmatrix ----------
__device__ __forceinline__ uint32_t smem_u32(const void* p) {
    uint32_t a;
    asm("{ .reg .u64 t; cvta.to.shared.u64 t,%1; cvt.u32.u64 %0,t; }" : "=r"(a) : "l"(p));
    return a;
}
__device__ __forceinline__ void ldsm4(uint32_t& r0, uint32_t& r1, uint32_t& r2,
                                      uint32_t& r3, uint32_t a) {
    asm volatile("ldmatrix.sync.aligned.m8n8.x4.shared.b16 {%0,%1,%2,%3},[%4];"
                 : "=r"(r0), "=r"(r1), "=r"(r2), "=r"(r3) : "r"(a));
}
__device__ __forceinline__ void ldsm2(uint32_t& r0, uint32_t& r1, uint32_t a) {
    asm volatile("ldmatrix.sync.aligned.m8n8.x2.shared.b16 {%0,%1},[%2];"
                 : "=r"(r0), "=r"(r1) : "r"(a));
}
__device__ __forceinline__ void mma16816(float* d, const uint32_t* a, const uint32_t* b) {
    asm volatile(
        "mma.sync.aligned.m16n8k16.row.col.f32.bf16.bf16.f32 "
        "{%0,%1,%2,%3},{%4,%5,%6,%7},{%8,%9},{%0,%1,%2,%3};"
        : "+f"(d[0]), "+f"(d[1]), "+f"(d[2]), "+f"(d[3])
        : "r"(a[0]), "r"(a[1]), "r"(a[2]), "r"(a[3]), "r"(b[0]), "r"(b[1]));
}

// ======================= projection (R11 + cp.async A staging) ===============
#define PSTR 528
#define SM_PBIAS 0
#define SM_BH 1024
#define SM_BL (SM_BH + 64 * PSTR)
#define SM_AH (SM_BL + 64 * PSTR)
#define SM_AL (SM_AH + 128 * PSTR)
#define SM_PROJ_TOT (SM_AL + 128 * PSTR)

__global__ void __launch_bounds__(256, 1) proj_mma_kernel(
    const float* __restrict__ bc, const float* __restrict__ ba,
    const float* __restrict__ bh)
{
    extern __shared__ __align__(1024) char smem[];
    const uint32_t sb = smem_u32(smem);
    const int tid = threadIdx.x;
    const int wid = tid >> 5;
    const int lane = tid & 31;

    const int n0 = blockIdx.x * 64;
    const int region = n0 >> 9;
    const int nl0 = n0 & 511;
    const float* __restrict__ bias = (region == 0) ? bc : (region == 1 ? ba : bh);
    float* biasS = (float*)(smem + SM_PBIAS);
    if (tid < 64) biasS[tid] = bias[nl0 + tid];

    const __nv_bfloat16* ubase_h = g_uh + (size_t)region * HID * INP;
    const __nv_bfloat16* ubase_l = g_ul + (size_t)region * HID * INP;
    for (int idx = tid; idx < 4096; idx += 256) {
        int sel = idx >> 11;
        int r = (idx >> 5) & 63, c = idx & 31;
        const __nv_bfloat16* src = (sel ? ubase_l : ubase_h) + (size_t)(nl0 + r) * INP;
        uint4 v = ((const uint4*)src)[c];
        *(uint4*)(smem + (sel ? SM_BL : SM_BH) + r * PSTR + c * 16) = v;
    }

    const int wm = wid & 3, wn = wid >> 2;
    const int msel = lane >> 3;
    const int arow = (msel & 1) * 8 + (lane & 7);
    const int acol16 = (msel >> 1);
    uint32_t a_base[2];
    #pragma unroll
    for (int mt = 0; mt < 2; mt++)
        a_base[mt] = sb + SM_AH + (wm * 32 + mt * 16 + arow) * PSTR + acol16 * 16;
    uint32_t b_base[4];
    #pragma unroll
    for (int nt = 0; nt < 4; nt++)
        b_base[nt] = sb + SM_BH + (wn * 32 + nt * 8 + (lane & 7)) * PSTR
                   + ((lane >> 3) & 1) * 16;
    const uint32_t ADL = SM_AL - SM_AH;
    const uint32_t BDL = SM_BL - SM_BH;

    for (int i = 0; i < 8; i++) {
        const int m0 = (blockIdx.y * 8 + i) * 128;
        __syncthreads();

        // cp.async A staging (hi+lo planes)
        for (int idx = tid; idx < 8192; idx += 256) {
            int sel = idx >> 12;
            int r = (idx >> 5) & 127, c = idx & 31;
            const __nv_bfloat16* src = (sel ? g_xl : g_xh) + (size_t)(m0 + r) * INP;
            const void* gaddr = (const char*)src + c * 16;
            uint32_t daddr = sb + (sel ? SM_AL : SM_AH) + r * PSTR + c * 16;
            asm volatile("cp.async.ca.shared.global [%0],[%1],16;"
                         :: "r"(daddr), "l"(gaddr) : "memory");
        }
        asm volatile("cp.async.commit_group;" ::: "memory");
        asm volatile("cp.async.wait_group 0;" ::: "memory");
        __syncthreads();

        float acc[2][4][4];
        #pragma unroll
        for (int mt = 0; mt < 2; mt++)
            #pragma unroll
            for (int nt = 0; nt < 4; nt++)
                #pragma unroll
                for (int q = 0; q < 4; q++) acc[mt][nt][q] = 0.0f;

        #pragma unroll 4
        for (int ks = 0; ks < 16; ks++) {
            const uint32_t kb = ks * 32;
            uint32_t bhf[4][2], blf[4][2];
            #pragma unroll
            for (int nt = 0; nt < 4; nt++) {
                ldsm2(bhf[nt][0], bhf[nt][1], b_base[nt] + kb);
                ldsm2(blf[nt][0], blf[nt][1], b_base[nt] + BDL + kb);
            }
            uint32_t ahf[2][4], alf[2][4];
            #pragma unroll
            for (int mt = 0; mt < 2; mt++) {
                ldsm4(ahf[mt][0], ahf[mt][1], ahf[mt][2], ahf[mt][3], a_base[mt] + kb);
                ldsm4(alf[mt][0], alf[mt][1], alf[mt][2], alf[mt][3],
                      a_base[mt] + ADL + kb);
            }
            #pragma unroll
            for (int mt = 0; mt < 2; mt++)
                #pragma unroll
                for (int nt = 0; nt < 4; nt++)
                    mma16816(acc[mt][nt], ahf[mt], bhf[nt]);
            #pragma unroll
            for (int mt = 0; mt < 2; mt++)
                #pragma unroll
                for (int nt = 0; nt < 4; nt++)
                    mma16816(acc[mt][nt], ahf[mt], blf[nt]);
            #pragma unroll
            for (int mt = 0; mt < 2; mt++)
                #pragma unroll
                for (int nt = 0; nt < 4; nt++)
                    mma16816(acc[mt][nt], alf[mt], bhf[nt]);
        }

        const int gid = lane >> 2, tig = lane & 3;
        #pragma unroll
        for (int mt = 0; mt < 2; mt++) {
            const int r0 = m0 + wm * 32 + mt * 16 + gid;
            #pragma unroll
            for (int nt = 0; nt < 4; nt++) {
                const int cl = wn * 32 + nt * 8 + tig * 2;
                float b0 = biasS[cl], b1 = biasS[cl + 1];
                float* d0 = &g_xp[(size_t)r0 * 1536 + n0 + cl];
                float* d1 = &g_xp[(size_t)(r0 + 8) * 1536 + n0 + cl];
                *(float2*)d0 = make_float2(acc[mt][nt][0] + b0, acc[mt][nt][1] + b1);
                *(float2*)d1 = make_float2(acc[mt][nt][2] + b0, acc[mt][nt][3] + b1);
            }
        }
    }
}

// ======================= recurrence v12: distributed flag barrier ============
// = R14 (verified 4402us) with the counting-atomic barrier replaced by
// per-CTA release flags + 16-lane parallel polling. No atomic serialization,
// no winner-broadcast hop. All math/mappings/stores identical.
#define WSTR   1040
#define SM_WHC 0
#define SM_WHA 66560
#define SM_HH  133120
#define SM_HL  166400
#define SM_RED 199680
#define SM_REC_TOT 232448
#define LODELTA 33280
#define SM_G0   1024                       // pad hole of W row 0 (bytes 1024..1039)

__global__ void __launch_bounds__(512, 1) recur_kernel(
    const float* __restrict__ h_in,
    const float* __restrict__ Wc, const float* __restrict__ Wa,
    float* __restrict__ out)
{
    extern __shared__ __align__(1024) char smem[];
    const uint32_t sb = smem_u32(smem);
    float4* RedF4 = (float4*)(smem + SM_RED);
    const float2* RedF2 = (const float2*)(smem + SM_RED);

    const int ct = blockIdx.x;
    const int jt = ct & 15, bt = ct >> 4;
    const int j0 = jt * 32, b0 = bt * 32;
    const int tid = threadIdx.x;
    const int w = tid >> 5, lane = tid & 31;
    const int ks = w & 3, mat = (w >> 2) & 1, mt = w >> 3;

    // ldmatrix bases (identical to R14)
    const int msel = lane >> 3;
    const uint32_t abase = sb + SM_HH +
        (mt * 16 + (msel & 1) * 8 + (lane & 7)) * WSTR + (msel >> 1) * 16;
    uint32_t b_base[4];
    #pragma unroll
    for (int nt = 0; nt < 4; nt++)
        b_base[nt] = sb + (mat ? SM_WHA : SM_WHC) +
            (nt * 8 + (lane & 7)) * WSTR + ((lane >> 3) & 1) * 16;

    // consumer mapping (identical to R14)
    const int cb = tid >> 4, jp = tid & 15;
    const int cmt = cb >> 4, cqh = (cb >> 3) & 1, cgid = cb & 7;
    const int clane = cgid * 4 + (jp & 3);
    const int cntc = jp >> 2;
    const int cfbase = cmt * 4 * 128 + clane * 4 + cntc;

    const int preg = mat * 8 + mt * 4 + ks;

    unsigned* myflag = &g_flags[bt][jt];

    // stash replay-safe generation base (own flag: race-free) in smem pad hole
    if (tid == 0) *(unsigned*)(smem + SM_G0) = *myflag;

    // ---- one-time: stage W hi/lo (both mats) ----
    for (int idx = tid; idx < 8192; idx += 512) {
        int m = idx >> 12;
        int j = (idx >> 7) & 31;
        int kc = idx & 127;
        const float* src = (m ? Wa : Wc) + (size_t)(j0 + j) * HID + kc * 4;
        float4 v = __ldcg((const float4*)src);
        uint2 hi, lo; split4(v, hi, lo);
        char* bp = smem + (m ? SM_WHA : SM_WHC) + j * WSTR + kc * 8;
        *(uint2*)bp = hi;
        *(uint2*)(bp + LODELTA) = lo;
    }

    // xp prefetch t=0
    float2 xc, xa, xh;
    {
        const size_t crow0 = (size_t)b0 + cb;
        const float* xpb = &g_xp[crow0 * 1536 + j0 + jp * 2];
        xc = __ldcg((const float2*)(xpb));
        xa = __ldcg((const float2*)(xpb + 512));
        xh = __ldcg((const float2*)(xpb + 1024));
    }

    unsigned g0 = 0;

    for (int t = 0; t < SEQ; t++) {
        // ---- stage h tile ----
        if (t == 0) {
            for (int i = tid; i < 32 * 128; i += 512) {
                int r = i >> 7, kc = i & 127;
                float4 v = __ldcg((const float4*)&h_in[(size_t)(b0 + r) * HID + kc * 4]);
                uint2 hi, lo; split4(v, hi, lo);
                char* bp = smem + SM_HH + r * WSTR + kc * 8;
                *(uint2*)bp = hi;
                *(uint2*)(bp + LODELTA) = lo;
            }
        } else {
            const uint32_t* srcb = g_hb[t & 1][0];
            const uint32_t* srcl = g_hb[t & 1][1];
            for (int i = tid; i < 4096; i += 512) {
                int plane = i >> 11;
                int rem = i & 2047;
                int r = rem >> 6;
                int c = rem & 63;
                const uint32_t* src = plane ? srcl : srcb;
                const void* gaddr = (const char*)src + ((size_t)(b0 + r) * 64 + c) * 16;
                uint32_t daddr = sb + (plane ? SM_HL : SM_HH) + r * WSTR + c * 16;
                asm volatile("cp.async.ca.shared.global [%0],[%1],16;"
                             :: "r"(daddr), "l"(gaddr) : "memory");
            }
            asm volatile("cp.async.commit_group;" ::: "memory");
            asm volatile("cp.async.wait_group 0;" ::: "memory");
        }
        __syncthreads();
        if (t == 0) g0 = *(const unsigned*)(smem + SM_G0);   // broadcast LDS

        // ---- HMMA matvec (identical to R14) ----
        float acc[4][4];
        #pragma unroll
        for (int nt = 0; nt < 4; nt++)
            #pragma unroll
            for (int q = 0; q < 4; q++) acc[nt][q] = 0.0f;

        #pragma unroll
        for (int kstep = 0; kstep < 8; kstep++) {
            const uint32_t kb = ks * 256 + kstep * 32;
            uint32_t ahf[4], alf[4];
            ldsm4(ahf[0], ahf[1], ahf[2], ahf[3], abase + kb);
            ldsm4(alf[0], alf[1], alf[2], alf[3], abase + LODELTA + kb);
            uint32_t bhf[4][2], blf[4][2];
            #pragma unroll
            for (int nt = 0; nt < 4; nt++) {
                ldsm2(bhf[nt][0], bhf[nt][1], b_base[nt] + kb);
                ldsm2(blf[nt][0], blf[nt][1], b_base[nt] + LODELTA + kb);
            }
            #pragma unroll
            for (int nt = 0; nt < 4; nt++) {
                mma16816(acc[nt], ahf, bhf[nt]);
                mma16816(acc[nt], ahf, blf[nt]);
                mma16816(acc[nt], alf, bhf[nt]);
            }
        }

        // ---- single-round reduction (identical to R14) ----
        #pragma unroll
        for (int nt = 0; nt < 4; nt++)
            RedF4[preg * 128 + lane * 4 + nt] =
                make_float4(acc[nt][0], acc[nt][1], acc[nt][2], acc[nt][3]);
        __syncthreads();

        // ---- consumer: sum 4 partials, epilogue (identical to R14) ----
        {
            float2 rc[4], ra[4];
            #pragma unroll
            for (int r = 0; r < 4; r++) {
                rc[r] = RedF2[(cfbase + r * 128) * 2 + cqh];
                ra[r] = RedF2[(cfbase + 1024 + r * 128) * 2 + cqh];
            }
            float2 hc = make_float2((rc[0].x + rc[2].x) + (rc[1].x + rc[3].x),
                                    (rc[0].y + rc[2].y) + (rc[1].y + rc[3].y));
            float2 ha = make_float2((ra[0].x + ra[2].x) + (ra[1].x + ra[3].x),
                                    (ra[0].y + ra[2].y) + (ra[1].y + ra[3].y));

            const uint32_t hb = *(const uint32_t*)(smem + SM_HH + cb * WSTR +
                                                   (j0 + jp * 2) * 2);
            const uint32_t lb = *(const uint32_t*)(smem + SM_HL + cb * WSTR +
                                                   (j0 + jp * 2) * 2);
            float hp0 = __bfloat162float(__ushort_as_bfloat16((unsigned short)(hb & 0xFFFF)))
                      + __bfloat162float(__ushort_as_bfloat16((unsigned short)(lb & 0xFFFF)));
            float hp1 = __bfloat162float(__ushort_as_bfloat16((unsigned short)(hb >> 16)))
                      + __bfloat162float(__ushort_as_bfloat16((unsigned short)(lb >> 16)));

            const size_t crow = (size_t)t * BATCH + b0 + cb;
            float r0, r1;
            {
                float cg = sig_f(xc.x + hc.x);
                float ag = 1.0f + tanh_f(xa.x + ha.x);
                r0 = cg * hp0 + (1.0f - cg) * tanh_f(xh.x + ag * hp0);
            }
            {
                float cg = sig_f(xc.y + hc.y);
                float ag = 1.0f + tanh_f(xa.y + ha.y);
                r1 = cg * hp1 + (1.0f - cg) * tanh_f(xh.y + ag * hp1);
            }
            *(float2*)&out[crow * HID + j0 + jp * 2] = make_float2(r0, r1);
            __nv_bfloat16 h0b = __float2bfloat16_rn(r0);
            __nv_bfloat16 h1b = __float2bfloat16_rn(r1);
            __nv_bfloat16 l0b = __float2bfloat16_rn(r0 - __bfloat162float(h0b));
            __nv_bfloat16 l1b = __float2bfloat16_rn(r1 - __bfloat162float(h1b));
            const int hidx = (b0 + cb) * 256 + (j0 >> 1) + jp;
            g_hb[(t + 1) & 1][0][hidx] = pck(h0b, h1b);
            g_hb[(t + 1) & 1][1][hidx] = pck(l0b, l1b);
            if (t == SEQ - 1)
                *(float2*)&out[(size_t)SEQ * BATCH * HID +
                               (size_t)(b0 + cb) * HID + j0 + jp * 2] =
                    make_float2(r0, r1);
        }

        // ---- prefetch next xp, then distributed flag barrier ----
        if (t < SEQ - 1) {
            const size_t nrow = (size_t)(t + 1) * BATCH + b0 + cb;
            const float* nxpb = &g_xp[nrow * 1536 + j0 + jp * 2];
            xc = __ldcg((const float2*)(nxpb));
            xa = __ldcg((const float2*)(nxpb + 512));
            xh = __ldcg((const float2*)(nxpb + 1024));

            __syncthreads();                       // g_hb writes done CTA-wide
            {
                const unsigned target = g0 + (unsigned)t + 1u;
                if (tid == 0) st_rel(myflag, target);        // publish own slice
                if (tid < 16) {                              // parallel poll
                    const unsigned* f = &g_flags[bt][tid];
                    while (ld_acq(f) < target) { }
                }
            }
            __syncthreads();
        }
    }
}

// ============================================================================
extern "C" void kernel_launch(void* const* d_in, const int* in_sizes, int n_in,
                              void* d_out, int out_size)
{
    const float* X  = (const float*)d_in[0];
    const float* h0 = (const float*)d_in[1];
    const float* Uc = (const float*)d_in[2];
    const float* Wc = (const float*)d_in[3];
    const float* bc = (const float*)d_in[4];
    const float* Ua = (const float*)d_in[5];
    const float* Wa = (const float*)d_in[6];
    const float* ba = (const float*)d_in[7];
    const float* Uh = (const float*)d_in[8];
    const float* bh = (const float*)d_in[9];
    float* out = (float*)d_out;

    cudaFuncSetAttribute(proj_mma_kernel, cudaFuncAttributeMaxDynamicSharedMemorySize,
                         SM_PROJ_TOT);
    cudaFuncSetAttribute(recur_kernel, cudaFuncAttributeMaxDynamicSharedMemorySize,
                         SM_REC_TOT);

    xsplit_kernel<<<4096, 256>>>(X);
    usplit_kernel<<<384, 256>>>(Uc, Ua, Uh);
    dim3 pg(24, 128);
    proj_mma_kernel<<<pg, 256, SM_PROJ_TOT>>>(bc, ba, bh);
    recur_kernel<<<128, 512, SM_REC_TOT>>>(h0, Wc, Wa, out);
}

// round 16
// speedup vs baseline: 1.2308x; 1.2308x over previous
#include <cuda_runtime.h>
#include <cuda_bf16.h>
#include <cstddef>
#include <cstdint>
#include <math.h>

#define SEQ   512
#define BATCH 256
#define INP   256
#define HID   512

typedef unsigned long long u64;

// ---------- sync helpers ----------
__device__ __forceinline__ unsigned ld_acq(const unsigned* p) {
    unsigned v;
    asm volatile("ld.acquire.gpu.global.b32 %0,[%1];" : "=r"(v) : "l"(p) : "memory");
    return v;
}
__device__ __forceinline__ void st_rel(unsigned* p, unsigned v) {
    asm volatile("st.release.gpu.global.b32 [%0],%1;" :: "l"(p), "r"(v) : "memory");
}
__device__ __forceinline__ unsigned atom_add_acqrel(unsigned* p, unsigned v) {
    unsigned old;
    asm volatile("atom.add.acq_rel.gpu.global.u32 %0,[%1],%2;"
                 : "=r"(old) : "l"(p), "r"(v) : "memory");
    return old;
}

// ---------- fast activations ----------
__device__ __forceinline__ float sig_f(float z) {
    return __fdividef(1.0f, 1.0f + __expf(-z));
}
__device__ __forceinline__ float tanh_f(float z) {
    return 1.0f - __fdividef(2.0f, __expf(2.0f * z) + 1.0f);
}

// ---------- scratch ----------
__device__ float g_xp[(size_t)SEQ * BATCH * 3 * HID];
__device__ uint32_t g_hb[2][2][BATCH * HID / 2];   // [buf][plane hi/lo][b*256 + j/2]
__device__ unsigned g_cnt[8 * 32];
__device__ unsigned g_gen[8 * 32];
__device__ __nv_bfloat16 g_xh[(size_t)SEQ * BATCH * INP];
__device__ __nv_bfloat16 g_xl[(size_t)SEQ * BATCH * INP];
__device__ __nv_bfloat16 g_uh[3 * HID * INP];
__device__ __nv_bfloat16 g_ul[3 * HID * INP];

// ---------- split helpers ----------
__device__ __forceinline__ uint32_t pck(__nv_bfloat16 a, __nv_bfloat16 b) {
    return (uint32_t)__bfloat16_as_ushort(a) | ((uint32_t)__bfloat16_as_ushort(b) << 16);
}
__device__ __forceinline__ void split4(float4 v, uint2& hi, uint2& lo) {
    __nv_bfloat16 h0 = __float2bfloat16_rn(v.x), h1 = __float2bfloat16_rn(v.y);
    __nv_bfloat16 h2 = __float2bfloat16_rn(v.z), h3 = __float2bfloat16_rn(v.w);
    __nv_bfloat16 l0 = __float2bfloat16_rn(v.x - __bfloat162float(h0));
    __nv_bfloat16 l1 = __float2bfloat16_rn(v.y - __bfloat162float(h1));
    __nv_bfloat16 l2 = __float2bfloat16_rn(v.z - __bfloat162float(h2));
    __nv_bfloat16 l3 = __float2bfloat16_rn(v.w - __bfloat162float(h3));
    hi = make_uint2(pck(h0, h1), pck(h2, h3));
    lo = make_uint2(pck(l0, l1), pck(l2, l3));
}

__global__ void __launch_bounds__(256) xsplit_kernel(const float* __restrict__ X) {
    const size_t total = (size_t)SEQ * BATCH * INP / 4;
    for (size_t f4 = (size_t)blockIdx.x * 256 + threadIdx.x; f4 < total;
         f4 += (size_t)gridDim.x * 256) {
        float4 v = __ldcg((const float4*)X + f4);
        uint2 hi, lo; split4(v, hi, lo);
        ((uint2*)g_xh)[f4] = hi;
        ((uint2*)g_xl)[f4] = lo;
    }
}

__global__ void __launch_bounds__(256) usplit_kernel(
    const float* __restrict__ Uc, const float* __restrict__ Ua,
    const float* __restrict__ Uh)
{
    const int mat = blockIdx.x >> 7;
    const int f4 = (blockIdx.x & 127) * 256 + threadIdx.x;
    const float* src = (mat == 0) ? Uc : (mat == 1 ? Ua : Uh);
    float4 v = __ldcg((const float4*)src + f4);
    uint2 hi, lo; split4(v, hi, lo);
    ((uint2*)g_uh)[mat * 32768 + f4] = hi;
    ((uint2*)g_ul)[mat * 32768 + f4] = lo;
}

// ---------- mma / ldmatrix ----------
__device__ __forceinline__ uint32_t smem_u32(const void* p) {
    uint32_t a;
    asm("{ .reg .u64 t; cvta.to.shared.u64 t,%1; cvt.u32.u64 %0,t; }" : "=r"(a) : "l"(p));
    return a;
}
__device__ __forceinline__ void ldsm4(uint32_t& r0, uint32_t& r1, uint32_t& r2,
                                      uint32_t& r3, uint32_t a) {
    asm volatile("ldmatrix.sync.aligned.m8n8.x4.shared.b16 {%0,%1,%2,%3},[%4];"
                 : "=r"(r0), "=r"(r1), "=r"(r2), "=r"(r3) : "r"(a));
}
__device__ __forceinline__ void ldsm2(uint32_t& r0, uint32_t& r1, uint32_t a) {
    asm volatile("ldmatrix.sync.aligned.m8n8.x2.shared.b16 {%0,%1},[%2];"
                 : "=r"(r0), "=r"(r1) : "r"(a));
}
__device__ __forceinline__ void mma16816(float* d, const uint32_t* a, const uint32_t* b) {
    asm volatile(
        "mma.sync.aligned.m16n8k16.row.col.f32.bf16.bf16.f32 "
        "{%0,%1,%2,%3},{%4,%5,%6,%7},{%8,%9},{%0,%1,%2,%3};"
        : "+f"(d[0]), "+f"(d[1]), "+f"(d[2]), "+f"(d[3])
        : "r"(a[0]), "r"(a[1]), "r"(a[2]), "r"(a[3]), "r"(b[0]), "r"(b[1]));
}

// ======================= projection (R11 + cp.async A staging) ===============
#define PSTR 528
#define SM_PBIAS 0
#define SM_BH 1024
#define SM_BL (SM_BH + 64 * PSTR)
#define SM_AH (SM_BL + 64 * PSTR)
#define SM_AL (SM_AH + 128 * PSTR)
#define SM_PROJ_TOT (SM_AL + 128 * PSTR)

__global__ void __launch_bounds__(256, 1) proj_mma_kernel(
    const float* __restrict__ bc, const float* __restrict__ ba,
    const float* __restrict__ bh)
{
    extern __shared__ __align__(1024) char smem[];
    const uint32_t sb = smem_u32(smem);
    const int tid = threadIdx.x;
    const int wid = tid >> 5;
    const int lane = tid & 31;

    const int n0 = blockIdx.x * 64;
    const int region = n0 >> 9;
    const int nl0 = n0 & 511;
    const float* __restrict__ bias = (region == 0) ? bc : (region == 1 ? ba : bh);
    float* biasS = (float*)(smem + SM_PBIAS);
    if (tid < 64) biasS[tid] = bias[nl0 + tid];

    const __nv_bfloat16* ubase_h = g_uh + (size_t)region * HID * INP;
    const __nv_bfloat16* ubase_l = g_ul + (size_t)region * HID * INP;
    for (int idx = tid; idx < 4096; idx += 256) {
        int sel = idx >> 11;
        int r = (idx >> 5) & 63, c = idx & 31;
        const __nv_bfloat16* src = (sel ? ubase_l : ubase_h) + (size_t)(nl0 + r) * INP;
        uint4 v = ((const uint4*)src)[c];
        *(uint4*)(smem + (sel ? SM_BL : SM_BH) + r * PSTR + c * 16) = v;
    }

    const int wm = wid & 3, wn = wid >> 2;
    const int msel = lane >> 3;
    const int arow = (msel & 1) * 8 + (lane & 7);
    const int acol16 = (msel >> 1);
    uint32_t a_base[2];
    #pragma unroll
    for (int mt = 0; mt < 2; mt++)
        a_base[mt] = sb + SM_AH + (wm * 32 + mt * 16 + arow) * PSTR + acol16 * 16;
    uint32_t b_base[4];
    #pragma unroll
    for (int nt = 0; nt < 4; nt++)
        b_base[nt] = sb + SM_BH + (wn * 32 + nt * 8 + (lane & 7)) * PSTR
                   + ((lane >> 3) & 1) * 16;
    const uint32_t ADL = SM_AL - SM_AH;
    const uint32_t BDL = SM_BL - SM_BH;

    for (int i = 0; i < 8; i++) {
        const int m0 = (blockIdx.y * 8 + i) * 128;
        __syncthreads();

        // cp.async A staging (hi+lo planes) — THE isolated delta vs R14
        for (int idx = tid; idx < 8192; idx += 256) {
            int sel = idx >> 12;
            int r = (idx >> 5) & 127, c = idx & 31;
            const __nv_bfloat16* src = (sel ? g_xl : g_xh) + (size_t)(m0 + r) * INP;
            const void* gaddr = (const char*)src + c * 16;
            uint32_t daddr = sb + (sel ? SM_AL : SM_AH) + r * PSTR + c * 16;
            asm volatile("cp.async.ca.shared.global [%0],[%1],16;"
                         :: "r"(daddr), "l"(gaddr) : "memory");
        }
        asm volatile("cp.async.commit_group;" ::: "memory");
        asm volatile("cp.async.wait_group 0;" ::: "memory");
        __syncthreads();

        float acc[2][4][4];
        #pragma unroll
        for (int mt = 0; mt < 2; mt++)
            #pragma unroll
            for (int nt = 0; nt < 4; nt++)
                #pragma unroll
                for (int q = 0; q < 4; q++) acc[mt][nt][q] = 0.0f;

        #pragma unroll 4
        for (int ks = 0; ks < 16; ks++) {
            const uint32_t kb = ks * 32;
            uint32_t bhf[4][2], blf[4][2];
            #pragma unroll
            for (int nt = 0; nt < 4; nt++) {
                ldsm2(bhf[nt][0], bhf[nt][1], b_base[nt] + kb);
                ldsm2(blf[nt][0], blf[nt][1], b_base[nt] + BDL + kb);
            }
            uint32_t ahf[2][4], alf[2][4];
            #pragma unroll
            for (int mt = 0; mt < 2; mt++) {
                ldsm4(ahf[mt][0], ahf[mt][1], ahf[mt][2], ahf[mt][3], a_base[mt] + kb);
                ldsm4(alf[mt][0], alf[mt][1], alf[mt][2], alf[mt][3],
                      a_base[mt] + ADL + kb);
            }
            #pragma unroll
            for (int mt = 0; mt < 2; mt++)
                #pragma unroll
                for (int nt = 0; nt < 4; nt++)
                    mma16816(acc[mt][nt], ahf[mt], bhf[nt]);
            #pragma unroll
            for (int mt = 0; mt < 2; mt++)
                #pragma unroll
                for (int nt = 0; nt < 4; nt++)
                    mma16816(acc[mt][nt], ahf[mt], blf[nt]);
            #pragma unroll
            for (int mt = 0; mt < 2; mt++)
                #pragma unroll
                for (int nt = 0; nt < 4; nt++)
                    mma16816(acc[mt][nt], alf[mt], bhf[nt]);
        }

        const int gid = lane >> 2, tig = lane & 3;
        #pragma unroll
        for (int mt = 0; mt < 2; mt++) {
            const int r0 = m0 + wm * 32 + mt * 16 + gid;
            #pragma unroll
            for (int nt = 0; nt < 4; nt++) {
                const int cl = wn * 32 + nt * 8 + tig * 2;
                float b0 = biasS[cl], b1 = biasS[cl + 1];
                float* d0 = &g_xp[(size_t)r0 * 1536 + n0 + cl];
                float* d1 = &g_xp[(size_t)(r0 + 8) * 1536 + n0 + cl];
                *(float2*)d0 = make_float2(acc[mt][nt][0] + b0, acc[mt][nt][1] + b1);
                *(float2*)d1 = make_float2(acc[mt][nt][2] + b0, acc[mt][nt][3] + b1);
            }
        }
    }
}

// ======================= recurrence v11 (EXACT R14, verified 4402us) =========
#define WSTR   1040
#define SM_WHC 0
#define SM_WHA 66560
#define SM_HH  133120
#define SM_HL  166400
#define SM_RED 199680
#define SM_REC_TOT 232448
#define LODELTA 33280

__global__ void __launch_bounds__(512, 1) recur_kernel(
    const float* __restrict__ h_in,
    const float* __restrict__ Wc, const float* __restrict__ Wa,
    float* __restrict__ out)
{
    extern __shared__ __align__(1024) char smem[];
    const uint32_t sb = smem_u32(smem);
    float4* RedF4 = (float4*)(smem + SM_RED);
    const float2* RedF2 = (const float2*)(smem + SM_RED);

    const int ct = blockIdx.x;
    const int jt = ct & 15, bt = ct >> 4;
    const int j0 = jt * 32, b0 = bt * 32;
    const int tid = threadIdx.x;
    const int w = tid >> 5, lane = tid & 31;
    const int ks = w & 3, mat = (w >> 2) & 1, mt = w >> 3;

    const int msel = lane >> 3;
    const uint32_t abase = sb + SM_HH +
        (mt * 16 + (msel & 1) * 8 + (lane & 7)) * WSTR + (msel >> 1) * 16;
    uint32_t b_base[4];
    #pragma unroll
    for (int nt = 0; nt < 4; nt++)
        b_base[nt] = sb + (mat ? SM_WHA : SM_WHC) +
            (nt * 8 + (lane & 7)) * WSTR + ((lane >> 3) & 1) * 16;

    const int cb = tid >> 4, jp = tid & 15;
    const int cmt = cb >> 4, cqh = (cb >> 3) & 1, cgid = cb & 7;
    const int clane = cgid * 4 + (jp & 3);
    const int cntc = jp >> 2;
    const int cfbase = cmt * 4 * 128 + clane * 4 + cntc;

    const int preg = mat * 8 + mt * 4 + ks;

    // ---- one-time: stage W hi/lo (both mats) ----
    for (int idx = tid; idx < 8192; idx += 512) {
        int m = idx >> 12;
        int j = (idx >> 7) & 31;
        int kc = idx & 127;
        const float* src = (m ? Wa : Wc) + (size_t)(j0 + j) * HID + kc * 4;
        float4 v = __ldcg((const float4*)src);
        uint2 hi, lo; split4(v, hi, lo);
        char* bp = smem + (m ? SM_WHA : SM_WHC) + j * WSTR + kc * 8;
        *(uint2*)bp = hi;
        *(uint2*)(bp + LODELTA) = lo;
    }

    unsigned* cnt = &g_cnt[bt * 32];
    unsigned* gen = &g_gen[bt * 32];
    unsigned g0 = 0;
    if (tid == 0) g0 = *gen;   // safe: gen can't advance before this CTA arrives

    // xp prefetch t=0
    float2 xc, xa, xh;
    {
        const size_t crow0 = (size_t)b0 + cb;
        const float* xpb = &g_xp[crow0 * 1536 + j0 + jp * 2];
        xc = __ldcg((const float2*)(xpb));
        xa = __ldcg((const float2*)(xpb + 512));
        xh = __ldcg((const float2*)(xpb + 1024));
    }

    for (int t = 0; t < SEQ; t++) {
        // ---- stage h tile ----
        if (t == 0) {
            for (int i = tid; i < 32 * 128; i += 512) {
                int r = i >> 7, kc = i & 127;
                float4 v = __ldcg((const float4*)&h_in[(size_t)(b0 + r) * HID + kc * 4]);
                uint2 hi, lo; split4(v, hi, lo);
                char* bp = smem + SM_HH + r * WSTR + kc * 8;
                *(uint2*)bp = hi;
                *(uint2*)(bp + LODELTA) = lo;
            }
        } else {
            const uint32_t* srcb = g_hb[t & 1][0];
            const uint32_t* srcl = g_hb[t & 1][1];
            for (int i = tid; i < 4096; i += 512) {
                int plane = i >> 11;
                int rem = i & 2047;
                int r = rem >> 6;
                int c = rem & 63;
                const uint32_t* src = plane ? srcl : srcb;
                const void* gaddr = (const char*)src + ((size_t)(b0 + r) * 64 + c) * 16;
                uint32_t daddr = sb + (plane ? SM_HL : SM_HH) + r * WSTR + c * 16;
                asm volatile("cp.async.ca.shared.global [%0],[%1],16;"
                             :: "r"(daddr), "l"(gaddr) : "memory");
            }
            asm volatile("cp.async.commit_group;" ::: "memory");
            asm volatile("cp.async.wait_group 0;" ::: "memory");
        }
        __syncthreads();

        // ---- HMMA matvec ----
        float acc[4][4];
        #pragma unroll
        for (int nt = 0; nt < 4; nt++)
            #pragma unroll
            for (int q = 0; q < 4; q++) acc[nt][q] = 0.0f;

        #pragma unroll
        for (int kstep = 0; kstep < 8; kstep++) {
            const uint32_t kb = ks * 256 + kstep * 32;
            uint32_t ahf[4], alf[4];
            ldsm4(ahf[0], ahf[1], ahf[2], ahf[3], abase + kb);
            ldsm4(alf[0], alf[1], alf[2], alf[3], abase + LODELTA + kb);
            uint32_t bhf[4][2], blf[4][2];
            #pragma unroll
            for (int nt = 0; nt < 4; nt++) {
                ldsm2(bhf[nt][0], bhf[nt][1], b_base[nt] + kb);
                ldsm2(blf[nt][0], blf[nt][1], b_base[nt] + LODELTA + kb);
            }
            #pragma unroll
            for (int nt = 0; nt < 4; nt++) {
                mma16816(acc[nt], ahf, bhf[nt]);
                mma16816(acc[nt], ahf, blf[nt]);
                mma16816(acc[nt], alf, bhf[nt]);
            }
        }

        // ---- single-round reduction ----
        #pragma unroll
        for (int nt = 0; nt < 4; nt++)
            RedF4[preg * 128 + lane * 4 + nt] =
                make_float4(acc[nt][0], acc[nt][1], acc[nt][2], acc[nt][3]);
        __syncthreads();

        // ---- consumer: sum 4 partials, epilogue ----
        {
            float2 rc[4], ra[4];
            #pragma unroll
            for (int r = 0; r < 4; r++) {
                rc[r] = RedF2[(cfbase + r * 128) * 2 + cqh];
                ra[r] = RedF2[(cfbase + 1024 + r * 128) * 2 + cqh];
            }
            float2 hc = make_float2((rc[0].x + rc[2].x) + (rc[1].x + rc[3].x),
                                    (rc[0].y + rc[2].y) + (rc[1].y + rc[3].y));
            float2 ha = make_float2((ra[0].x + ra[2].x) + (ra[1].x + ra[3].x),
                                    (ra[0].y + ra[2].y) + (ra[1].y + ra[3].y));

            const uint32_t hb = *(const uint32_t*)(smem + SM_HH + cb * WSTR +
                                                   (j0 + jp * 2) * 2);
            const uint32_t lb = *(const uint32_t*)(smem + SM_HL + cb * WSTR +
                                                   (j0 + jp * 2) * 2);
            float hp0 = __bfloat162float(__ushort_as_bfloat16((unsigned short)(hb & 0xFFFF)))
                      + __bfloat162float(__ushort_as_bfloat16((unsigned short)(lb & 0xFFFF)));
            float hp1 = __bfloat162float(__ushort_as_bfloat16((unsigned short)(hb >> 16)))
                      + __bfloat162float(__ushort_as_bfloat16((unsigned short)(lb >> 16)));

            const size_t crow = (size_t)t * BATCH + b0 + cb;
            float r0, r1;
            {
                float cg = sig_f(xc.x + hc.x);
                float ag = 1.0f + tanh_f(xa.x + ha.x);
                r0 = cg * hp0 + (1.0f - cg) * tanh_f(xh.x + ag * hp0);
            }
            {
                float cg = sig_f(xc.y + hc.y);
                float ag = 1.0f + tanh_f(xa.y + ha.y);
                r1 = cg * hp1 + (1.0f - cg) * tanh_f(xh.y + ag * hp1);
            }
            *(float2*)&out[crow * HID + j0 + jp * 2] = make_float2(r0, r1);
            __nv_bfloat16 h0b = __float2bfloat16_rn(r0);
            __nv_bfloat16 h1b = __float2bfloat16_rn(r1);
            __nv_bfloat16 l0b = __float2bfloat16_rn(r0 - __bfloat162float(h0b));
            __nv_bfloat16 l1b = __float2bfloat16_rn(r1 - __bfloat162float(h1b));
            const int hidx = (b0 + cb) * 256 + (j0 >> 1) + jp;
            g_hb[(t + 1) & 1][0][hidx] = pck(h0b, h1b);
            g_hb[(t + 1) & 1][1][hidx] = pck(l0b, l1b);
            if (t == SEQ - 1)
                *(float2*)&out[(size_t)SEQ * BATCH * HID +
                               (size_t)(b0 + cb) * HID + j0 + jp * 2] =
                    make_float2(r0, r1);
        }

        // ---- prefetch next xp, then fence-fused counting barrier ----
        if (t < SEQ - 1) {
            const size_t nrow = (size_t)(t + 1) * BATCH + b0 + cb;
            const float* nxpb = &g_xp[nrow * 1536 + j0 + jp * 2];
            xc = __ldcg((const float2*)(nxpb));
            xa = __ldcg((const float2*)(nxpb + 512));
            xh = __ldcg((const float2*)(nxpb + 1024));

            __syncthreads();
            if (tid == 0) {
                const unsigned target = g0 + (unsigned)t + 1u;
                if (atom_add_acqrel(cnt, 1u) == 15u) {
                    atomicExch(cnt, 0u);
                    st_rel(gen, target);
                } else {
                    while (ld_acq(gen) != target) { }
                }
            }
            __syncthreads();
        }
    }
}

// ============================================================================
extern "C" void kernel_launch(void* const* d_in, const int* in_sizes, int n_in,
                              void* d_out, int out_size)
{
    const float* X  = (const float*)d_in[0];
    const float* h0 = (const float*)d_in[1];
    const float* Uc = (const float*)d_in[2];
    const float* Wc = (const float*)d_in[3];
    const float* bc = (const float*)d_in[4];
    const float* Ua = (const float*)d_in[5];
    const float* Wa = (const float*)d_in[6];
    const float* ba = (const float*)d_in[7];
    const float* Uh = (const float*)d_in[8];
    const float* bh = (const float*)d_in[9];
    float* out = (float*)d_out;

    cudaFuncSetAttribute(proj_mma_kernel, cudaFuncAttributeMaxDynamicSharedMemorySize,
                         SM_PROJ_TOT);
    cudaFuncSetAttribute(recur_kernel, cudaFuncAttributeMaxDynamicSharedMemorySize,
                         SM_REC_TOT);

    xsplit_kernel<<<4096, 256>>>(X);
    usplit_kernel<<<384, 256>>>(Uc, Ua, Uh);
    dim3 pg(24, 128);
    proj_mma_kernel<<<pg, 256, SM_PROJ_TOT>>>(bc, ba, bh);
    recur_kernel<<<128, 512, SM_REC_TOT>>>(h0, Wc, Wa, out);
}

// round 17
// speedup vs baseline: 1.2514x; 1.0168x over previous
#include <cuda_runtime.h>
#include <cuda_bf16.h>
#include <cstddef>
#include <cstdint>
#include <math.h>

#define SEQ   512
#define BATCH 256
#define INP   256
#define HID   512

typedef unsigned long long u64;

// ---------- sync helpers ----------
__device__ __forceinline__ unsigned ld_acq(const unsigned* p) {
    unsigned v;
    asm volatile("ld.acquire.gpu.global.b32 %0,[%1];" : "=r"(v) : "l"(p) : "memory");
    return v;
}
__device__ __forceinline__ void st_rel(unsigned* p, unsigned v) {
    asm volatile("st.release.gpu.global.b32 [%0],%1;" :: "l"(p), "r"(v) : "memory");
}
__device__ __forceinline__ unsigned atom_add_acqrel(unsigned* p, unsigned v) {
    unsigned old;
    asm volatile("atom.add.acq_rel.gpu.global.u32 %0,[%1],%2;"
                 : "=r"(old) : "l"(p), "r"(v) : "memory");
    return old;
}

// ---------- fast activations ----------
__device__ __forceinline__ float sig_f(float z) {
    return __fdividef(1.0f, 1.0f + __expf(-z));
}
__device__ __forceinline__ float tanh_f(float z) {
    return 1.0f - __fdividef(2.0f, __expf(2.0f * z) + 1.0f);
}

// ---------- scratch ----------
__device__ float g_xp[(size_t)SEQ * BATCH * 3 * HID];
__device__ uint32_t g_hb[2][2][BATCH * HID / 2];   // [buf][plane hi/lo][b*256 + j/2]
__device__ unsigned g_cnt[8 * 32];
__device__ unsigned g_gen[8 * 32];
__device__ __nv_bfloat16 g_xh[(size_t)SEQ * BATCH * INP];
__device__ __nv_bfloat16 g_xl[(size_t)SEQ * BATCH * INP];
__device__ __nv_bfloat16 g_uh[3 * HID * INP];
__device__ __nv_bfloat16 g_ul[3 * HID * INP];

// ---------- split helpers ----------
__device__ __forceinline__ uint32_t pck(__nv_bfloat16 a, __nv_bfloat16 b) {
    return (uint32_t)__bfloat16_as_ushort(a) | ((uint32_t)__bfloat16_as_ushort(b) << 16);
}
__device__ __forceinline__ void split4(float4 v, uint2& hi, uint2& lo) {
    __nv_bfloat16 h0 = __float2bfloat16_rn(v.x), h1 = __float2bfloat16_rn(v.y);
    __nv_bfloat16 h2 = __float2bfloat16_rn(v.z), h3 = __float2bfloat16_rn(v.w);
    __nv_bfloat16 l0 = __float2bfloat16_rn(v.x - __bfloat162float(h0));
    __nv_bfloat16 l1 = __float2bfloat16_rn(v.y - __bfloat162float(h1));
    __nv_bfloat16 l2 = __float2bfloat16_rn(v.z - __bfloat162float(h2));
    __nv_bfloat16 l3 = __float2bfloat16_rn(v.w - __bfloat162float(h3));
    hi = make_uint2(pck(h0, h1), pck(h2, h3));
    lo = make_uint2(pck(l0, l1), pck(l2, l3));
}

__global__ void __launch_bounds__(256) xsplit_kernel(const float* __restrict__ X) {
    const size_t total = (size_t)SEQ * BATCH * INP / 4;
    for (size_t f4 = (size_t)blockIdx.x * 256 + threadIdx.x; f4 < total;
         f4 += (size_t)gridDim.x * 256) {
        float4 v = __ldcg((const float4*)X + f4);
        uint2 hi, lo; split4(v, hi, lo);
        ((uint2*)g_xh)[f4] = hi;
        ((uint2*)g_xl)[f4] = lo;
    }
}

__global__ void __launch_bounds__(256) usplit_kernel(
    const float* __restrict__ Uc, const float* __restrict__ Ua,
    const float* __restrict__ Uh)
{
    const int mat = blockIdx.x >> 7;
    const int f4 = (blockIdx.x & 127) * 256 + threadIdx.x;
    const float* src = (mat == 0) ? Uc : (mat == 1 ? Ua : Uh);
    float4 v = __ldcg((const float4*)src + f4);
    uint2 hi, lo; split4(v, hi, lo);
    ((uint2*)g_uh)[mat * 32768 + f4] = hi;
    ((uint2*)g_ul)[mat * 32768 + f4] = lo;
}

// ---------- mma / ldmatrix ----------
__device__ __forceinline__ uint32_t smem_u32(const void* p) {
    uint32_t a;
    asm("{ .reg .u64 t; cvta.to.shared.u64 t,%1; cvt.u32.u64 %0,t; }" : "=r"(a) : "l"(p));
    return a;
}
__device__ __forceinline__ void ldsm4(uint32_t& r0, uint32_t& r1, uint32_t& r2,
                                      uint32_t& r3, uint32_t a) {
    asm volatile("ldmatrix.sync.aligned.m8n8.x4.shared.b16 {%0,%1,%2,%3},[%4];"
                 : "=r"(r0), "=r"(r1), "=r"(r2), "=r"(r3) : "r"(a));
}
__device__ __forceinline__ void ldsm2(uint32_t& r0, uint32_t& r1, uint32_t a) {
    asm volatile("ldmatrix.sync.aligned.m8n8.x2.shared.b16 {%0,%1},[%2];"
                 : "=r"(r0), "=r"(r1) : "r"(a));
}
__device__ __forceinline__ void mma16816(float* d, const uint32_t* a, const uint32_t* b) {
    asm volatile(
        "mma.sync.aligned.m16n8k16.row.col.f32.bf16.bf16.f32 "
        "{%0,%1,%2,%3},{%4,%5,%6,%7},{%8,%9},{%0,%1,%2,%3};"
        : "+f"(d[0]), "+f"(d[1]), "+f"(d[2]), "+f"(d[3])
        : "r"(a[0]), "r"(a[1]), "r"(a[2]), "r"(a[3]), "r"(b[0]), "r"(b[1]));
}

// ======================= projection v2: N=128 per CTA (A traffic halved) =====
// grid (12 n-pairs, 128 m-groups). B: 128 rows resident. A: 16 tiles x 64 rows.
// Warp grid 2m x 4n; warp tile 32m x 32n (register structure unchanged).
#define PSTR 528
#define SM_PBIAS 0
#define SM_BH 1024
#define SM_BL (SM_BH + 128 * PSTR)        //  68608
#define SM_AH (SM_BL + 128 * PSTR)        // 136192
#define SM_AL (SM_AH + 64 * PSTR)         // 169984
#define SM_PROJ_TOT (SM_AL + 64 * PSTR)   // 203776

__global__ void __launch_bounds__(256, 1) proj_mma_kernel(
    const float* __restrict__ bc, const float* __restrict__ ba,
    const float* __restrict__ bh)
{
    extern __shared__ __align__(1024) char smem[];
    const uint32_t sb = smem_u32(smem);
    const int tid = threadIdx.x;
    const int wid = tid >> 5;
    const int lane = tid & 31;

    const int n0 = blockIdx.x * 128;       // 12 pairs; pairs never cross regions
    const int region = n0 >> 9;
    const int nl0 = n0 & 511;
    const float* __restrict__ bias = (region == 0) ? bc : (region == 1 ? ba : bh);
    float* biasS = (float*)(smem + SM_PBIAS);
    if (tid < 128) biasS[tid] = bias[nl0 + tid];

    // ---- stage B (128n x 256k, hi+lo) one-time ----
    const __nv_bfloat16* ubase_h = g_uh + (size_t)region * HID * INP;
    const __nv_bfloat16* ubase_l = g_ul + (size_t)region * HID * INP;
    for (int idx = tid; idx < 8192; idx += 256) {     // 2 x 128 rows x 32 uint4
        int sel = idx >> 12;
        int r = (idx >> 5) & 127, c = idx & 31;
        const __nv_bfloat16* src = (sel ? ubase_l : ubase_h) + (size_t)(nl0 + r) * INP;
        uint4 v = ((const uint4*)src)[c];
        *(uint4*)(smem + (sel ? SM_BL : SM_BH) + r * PSTR + c * 16) = v;
    }

    const int wm = wid & 1, wn = wid >> 1;            // 2m x 4n warp grid
    const int msel = lane >> 3;
    const int arow = (msel & 1) * 8 + (lane & 7);
    const int acol16 = (msel >> 1);
    uint32_t a_base[2];
    #pragma unroll
    for (int mt = 0; mt < 2; mt++)
        a_base[mt] = sb + SM_AH + (wm * 32 + mt * 16 + arow) * PSTR + acol16 * 16;
    uint32_t b_base[4];
    #pragma unroll
    for (int nt = 0; nt < 4; nt++)
        b_base[nt] = sb + SM_BH + (wn * 32 + nt * 8 + (lane & 7)) * PSTR
                   + ((lane >> 3) & 1) * 16;
    const uint32_t ADL = SM_AL - SM_AH;
    const uint32_t BDL = SM_BL - SM_BH;

    for (int i = 0; i < 16; i++) {
        const int m0 = (blockIdx.y * 16 + i) * 64;
        __syncthreads();

        // cp.async A staging (64 rows, hi+lo planes)
        for (int idx = tid; idx < 4096; idx += 256) { // 2 x 64 rows x 32 uint4
            int sel = idx >> 11;
            int r = (idx >> 5) & 63, c = idx & 31;
            const __nv_bfloat16* src = (sel ? g_xl : g_xh) + (size_t)(m0 + r) * INP;
            const void* gaddr = (const char*)src + c * 16;
            uint32_t daddr = sb + (sel ? SM_AL : SM_AH) + r * PSTR + c * 16;
            asm volatile("cp.async.ca.shared.global [%0],[%1],16;"
                         :: "r"(daddr), "l"(gaddr) : "memory");
        }
        asm volatile("cp.async.commit_group;" ::: "memory");
        asm volatile("cp.async.wait_group 0;" ::: "memory");
        __syncthreads();

        float acc[2][4][4];
        #pragma unroll
        for (int mt = 0; mt < 2; mt++)
            #pragma unroll
            for (int nt = 0; nt < 4; nt++)
                #pragma unroll
                for (int q = 0; q < 4; q++) acc[mt][nt][q] = 0.0f;

        #pragma unroll 4
        for (int ks = 0; ks < 16; ks++) {
            const uint32_t kb = ks * 32;
            uint32_t bhf[4][2], blf[4][2];
            #pragma unroll
            for (int nt = 0; nt < 4; nt++) {
                ldsm2(bhf[nt][0], bhf[nt][1], b_base[nt] + kb);
                ldsm2(blf[nt][0], blf[nt][1], b_base[nt] + BDL + kb);
            }
            uint32_t ahf[2][4], alf[2][4];
            #pragma unroll
            for (int mt = 0; mt < 2; mt++) {
                ldsm4(ahf[mt][0], ahf[mt][1], ahf[mt][2], ahf[mt][3], a_base[mt] + kb);
                ldsm4(alf[mt][0], alf[mt][1], alf[mt][2], alf[mt][3],
                      a_base[mt] + ADL + kb);
            }
            #pragma unroll
            for (int mt = 0; mt < 2; mt++)
                #pragma unroll
                for (int nt = 0; nt < 4; nt++)
                    mma16816(acc[mt][nt], ahf[mt], bhf[nt]);
            #pragma unroll
            for (int mt = 0; mt < 2; mt++)
                #pragma unroll
                for (int nt = 0; nt < 4; nt++)
                    mma16816(acc[mt][nt], ahf[mt], blf[nt]);
            #pragma unroll
            for (int mt = 0; mt < 2; mt++)
                #pragma unroll
                for (int nt = 0; nt < 4; nt++)
                    mma16816(acc[mt][nt], alf[mt], bhf[nt]);
        }

        const int gid = lane >> 2, tig = lane & 3;
        #pragma unroll
        for (int mt = 0; mt < 2; mt++) {
            const int r0 = m0 + wm * 32 + mt * 16 + gid;
            #pragma unroll
            for (int nt = 0; nt < 4; nt++) {
                const int cl = wn * 32 + nt * 8 + tig * 2;
                float b0 = biasS[cl], b1 = biasS[cl + 1];
                float* d0 = &g_xp[(size_t)r0 * 1536 + n0 + cl];
                float* d1 = &g_xp[(size_t)(r0 + 8) * 1536 + n0 + cl];
                *(float2*)d0 = make_float2(acc[mt][nt][0] + b0, acc[mt][nt][1] + b1);
                *(float2*)d1 = make_float2(acc[mt][nt][2] + b0, acc[mt][nt][3] + b1);
            }
        }
    }
}

// ======================= recurrence v11 (EXACT R16, verified) ================
#define WSTR   1040
#define SM_WHC 0
#define SM_WHA 66560
#define SM_HH  133120
#define SM_HL  166400
#define SM_RED 199680
#define SM_REC_TOT 232448
#define LODELTA 33280

__global__ void __launch_bounds__(512, 1) recur_kernel(
    const float* __restrict__ h_in,
    const float* __restrict__ Wc, const float* __restrict__ Wa,
    float* __restrict__ out)
{
    extern __shared__ __align__(1024) char smem[];
    const uint32_t sb = smem_u32(smem);
    float4* RedF4 = (float4*)(smem + SM_RED);
    const float2* RedF2 = (const float2*)(smem + SM_RED);

    const int ct = blockIdx.x;
    const int jt = ct & 15, bt = ct >> 4;
    const int j0 = jt * 32, b0 = bt * 32;
    const int tid = threadIdx.x;
    const int w = tid >> 5, lane = tid & 31;
    const int ks = w & 3, mat = (w >> 2) & 1, mt = w >> 3;

    const int msel = lane >> 3;
    const uint32_t abase = sb + SM_HH +
        (mt * 16 + (msel & 1) * 8 + (lane & 7)) * WSTR + (msel >> 1) * 16;
    uint32_t b_base[4];
    #pragma unroll
    for (int nt = 0; nt < 4; nt++)
        b_base[nt] = sb + (mat ? SM_WHA : SM_WHC) +
            (nt * 8 + (lane & 7)) * WSTR + ((lane >> 3) & 1) * 16;

    const int cb = tid >> 4, jp = tid & 15;
    const int cmt = cb >> 4, cqh = (cb >> 3) & 1, cgid = cb & 7;
    const int clane = cgid * 4 + (jp & 3);
    const int cntc = jp >> 2;
    const int cfbase = cmt * 4 * 128 + clane * 4 + cntc;

    const int preg = mat * 8 + mt * 4 + ks;

    for (int idx = tid; idx < 8192; idx += 512) {
        int m = idx >> 12;
        int j = (idx >> 7) & 31;
        int kc = idx & 127;
        const float* src = (m ? Wa : Wc) + (size_t)(j0 + j) * HID + kc * 4;
        float4 v = __ldcg((const float4*)src);
        uint2 hi, lo; split4(v, hi, lo);
        char* bp = smem + (m ? SM_WHA : SM_WHC) + j * WSTR + kc * 8;
        *(uint2*)bp = hi;
        *(uint2*)(bp + LODELTA) = lo;
    }

    unsigned* cnt = &g_cnt[bt * 32];
    unsigned* gen = &g_gen[bt * 32];
    unsigned g0 = 0;
    if (tid == 0) g0 = *gen;

    float2 xc, xa, xh;
    {
        const size_t crow0 = (size_t)b0 + cb;
        const float* xpb = &g_xp[crow0 * 1536 + j0 + jp * 2];
        xc = __ldcg((const float2*)(xpb));
        xa = __ldcg((const float2*)(xpb + 512));
        xh = __ldcg((const float2*)(xpb + 1024));
    }

    for (int t = 0; t < SEQ; t++) {
        if (t == 0) {
            for (int i = tid; i < 32 * 128; i += 512) {
                int r = i >> 7, kc = i & 127;
                float4 v = __ldcg((const float4*)&h_in[(size_t)(b0 + r) * HID + kc * 4]);
                uint2 hi, lo; split4(v, hi, lo);
                char* bp = smem + SM_HH + r * WSTR + kc * 8;
                *(uint2*)bp = hi;
                *(uint2*)(bp + LODELTA) = lo;
            }
        } else {
            const uint32_t* srcb = g_hb[t & 1][0];
            const uint32_t* srcl = g_hb[t & 1][1];
            for (int i = tid; i < 4096; i += 512) {
                int plane = i >> 11;
                int rem = i & 2047;
                int r = rem >> 6;
                int c = rem & 63;
                const uint32_t* src = plane ? srcl : srcb;
                const void* gaddr = (const char*)src + ((size_t)(b0 + r) * 64 + c) * 16;
                uint32_t daddr = sb + (plane ? SM_HL : SM_HH) + r * WSTR + c * 16;
                asm volatile("cp.async.ca.shared.global [%0],[%1],16;"
                             :: "r"(daddr), "l"(gaddr) : "memory");
            }
            asm volatile("cp.async.commit_group;" ::: "memory");
            asm volatile("cp.async.wait_group 0;" ::: "memory");
        }
        __syncthreads();

        float acc[4][4];
        #pragma unroll
        for (int nt = 0; nt < 4; nt++)
            #pragma unroll
            for (int q = 0; q < 4; q++) acc[nt][q] = 0.0f;

        #pragma unroll
        for (int kstep = 0; kstep < 8; kstep++) {
            const uint32_t kb = ks * 256 + kstep * 32;
            uint32_t ahf[4], alf[4];
            ldsm4(ahf[0], ahf[1], ahf[2], ahf[3], abase + kb);
            ldsm4(alf[0], alf[1], alf[2], alf[3], abase + LODELTA + kb);
            uint32_t bhf[4][2], blf[4][2];
            #pragma unroll
            for (int nt = 0; nt < 4; nt++) {
                ldsm2(bhf[nt][0], bhf[nt][1], b_base[nt] + kb);
                ldsm2(blf[nt][0], blf[nt][1], b_base[nt] + LODELTA + kb);
            }
            #pragma unroll
            for (int nt = 0; nt < 4; nt++) {
                mma16816(acc[nt], ahf, bhf[nt]);
                mma16816(acc[nt], ahf, blf[nt]);
                mma16816(acc[nt], alf, bhf[nt]);
            }
        }

        #pragma unroll
        for (int nt = 0; nt < 4; nt++)
            RedF4[preg * 128 + lane * 4 + nt] =
                make_float4(acc[nt][0], acc[nt][1], acc[nt][2], acc[nt][3]);
        __syncthreads();

        {
            float2 rc[4], ra[4];
            #pragma unroll
            for (int r = 0; r < 4; r++) {
                rc[r] = RedF2[(cfbase + r * 128) * 2 + cqh];
                ra[r] = RedF2[(cfbase + 1024 + r * 128) * 2 + cqh];
            }
            float2 hc = make_float2((rc[0].x + rc[2].x) + (rc[1].x + rc[3].x),
                                    (rc[0].y + rc[2].y) + (rc[1].y + rc[3].y));
            float2 ha = make_float2((ra[0].x + ra[2].x) + (ra[1].x + ra[3].x),
                                    (ra[0].y + ra[2].y) + (ra[1].y + ra[3].y));

            const uint32_t hb = *(const uint32_t*)(smem + SM_HH + cb * WSTR +
                                                   (j0 + jp * 2) * 2);
            const uint32_t lb = *(const uint32_t*)(smem + SM_HL + cb * WSTR +
                                                   (j0 + jp * 2) * 2);
            float hp0 = __bfloat162float(__ushort_as_bfloat16((unsigned short)(hb & 0xFFFF)))
                      + __bfloat162float(__ushort_as_bfloat16((unsigned short)(lb & 0xFFFF)));
            float hp1 = __bfloat162float(__ushort_as_bfloat16((unsigned short)(hb >> 16)))
                      + __bfloat162float(__ushort_as_bfloat16((unsigned short)(lb >> 16)));

            const size_t crow = (size_t)t * BATCH + b0 + cb;
            float r0, r1;
            {
                float cg = sig_f(xc.x + hc.x);
                float ag = 1.0f + tanh_f(xa.x + ha.x);
                r0 = cg * hp0 + (1.0f - cg) * tanh_f(xh.x + ag * hp0);
            }
            {
                float cg = sig_f(xc.y + hc.y);
                float ag = 1.0f + tanh_f(xa.y + ha.y);
                r1 = cg * hp1 + (1.0f - cg) * tanh_f(xh.y + ag * hp1);
            }
            *(float2*)&out[crow * HID + j0 + jp * 2] = make_float2(r0, r1);
            __nv_bfloat16 h0b = __float2bfloat16_rn(r0);
            __nv_bfloat16 h1b = __float2bfloat16_rn(r1);
            __nv_bfloat16 l0b = __float2bfloat16_rn(r0 - __bfloat162float(h0b));
            __nv_bfloat16 l1b = __float2bfloat16_rn(r1 - __bfloat162float(h1b));
            const int hidx = (b0 + cb) * 256 + (j0 >> 1) + jp;
            g_hb[(t + 1) & 1][0][hidx] = pck(h0b, h1b);
            g_hb[(t + 1) & 1][1][hidx] = pck(l0b, l1b);
            if (t == SEQ - 1)
                *(float2*)&out[(size_t)SEQ * BATCH * HID +
                               (size_t)(b0 + cb) * HID + j0 + jp * 2] =
                    make_float2(r0, r1);
        }

        if (t < SEQ - 1) {
            const size_t nrow = (size_t)(t + 1) * BATCH + b0 + cb;
            const float* nxpb = &g_xp[nrow * 1536 + j0 + jp * 2];
            xc = __ldcg((const float2*)(nxpb));
            xa = __ldcg((const float2*)(nxpb + 512));
            xh = __ldcg((const float2*)(nxpb + 1024));

            __syncthreads();
            if (tid == 0) {
                const unsigned target = g0 + (unsigned)t + 1u;
                if (atom_add_acqrel(cnt, 1u) == 15u) {
                    atomicExch(cnt, 0u);
                    st_rel(gen, target);
                } else {
                    while (ld_acq(gen) != target) { }
                }
            }
            __syncthreads();
        }
    }
}

// ============================================================================
extern "C" void kernel_launch(void* const* d_in, const int* in_sizes, int n_in,
                              void* d_out, int out_size)
{
    const float* X  = (const float*)d_in[0];
    const float* h0 = (const float*)d_in[1];
    const float* Uc = (const float*)d_in[2];
    const float* Wc = (const float*)d_in[3];
    const float* bc = (const float*)d_in[4];
    const float* Ua = (const float*)d_in[5];
    const float* Wa = (const float*)d_in[6];
    const float* ba = (const float*)d_in[7];
    const float* Uh = (const float*)d_in[8];
    const float* bh = (const float*)d_in[9];
    float* out = (float*)d_out;

    cudaFuncSetAttribute(proj_mma_kernel, cudaFuncAttributeMaxDynamicSharedMemorySize,
                         SM_PROJ_TOT);
    cudaFuncSetAttribute(recur_kernel, cudaFuncAttributeMaxDynamicSharedMemorySize,
                         SM_REC_TOT);

    xsplit_kernel<<<4096, 256>>>(X);
    usplit_kernel<<<384, 256>>>(Uc, Ua, Uh);
    dim3 pg(12, 128);
    proj_mma_kernel<<<pg, 256, SM_PROJ_TOT>>>(bc, ba, bh);
    recur_kernel<<<128, 512, SM_REC_TOT>>>(h0, Wc, Wa, out);
}